// round 11
// baseline (speedup 1.0000x reference)
#include <cuda_runtime.h>
#include <math.h>

#define DIM   768
#define SEQ   1024
#define BATCH 8
#define NTOK  (BATCH*SEQ)      // 8192
#define NH    12
#define HD    64
#define KP    64
#define MLPH  3072
#define X_ELEMS (NTOK*DIM)     // 6291456

// ---------------- scratch (device globals; no allocation allowed) ----------
__device__ float g_n1 [NTOK*DIM];
__device__ float g_un [NTOK*DIM];
__device__ float g_qkv[NTOK*3*DIM];
__device__ float g_ao [NTOK*DIM];
__device__ float g_y  [NTOK*DIM];
__device__ float g_cph[NTOK*KP];
__device__ float g_zin[NTOK*DIM];
__device__ float g_xa [NTOK*DIM];
__device__ float g_n2 [NTOK*DIM];
__device__ float g_hid[NTOK*MLPH];
__device__ float g_Pn [KP*DIM];

// ---------------- packed fp32x2 helpers (sm_103a FFMA2) --------------------
__device__ __forceinline__ unsigned long long pk2(float lo, float hi){
    unsigned long long r;
    asm("mov.b64 %0, {%1, %2};" : "=l"(r) : "f"(lo), "f"(hi));
    return r;
}
__device__ __forceinline__ void fma2(unsigned long long& d,
                                     unsigned long long a, unsigned long long b){
    asm("fma.rn.f32x2 %0, %1, %2, %0;" : "+l"(d) : "l"(a), "l"(b));
}
__device__ __forceinline__ void mul2(unsigned long long& d, unsigned long long a){
    asm("mul.rn.f32x2 %0, %0, %1;" : "+l"(d) : "l"(a));
}
__device__ __forceinline__ float2 upk(unsigned long long v){
    float2 r;
    asm("mov.b64 {%0, %1}, %2;" : "=f"(r.x), "=f"(r.y) : "l"(v));
    return r;
}
__device__ __forceinline__ float gelu_f(float x){
    return 0.5f*x*(1.0f + erff(x*0.70710678118654752440f));
}

// ---------------- block reduction (256 threads) -----------------------------
__device__ __forceinline__ float blockReduceSum256(float v){
    __shared__ float sh[8];
    #pragma unroll
    for (int m=16; m>0; m>>=1) v += __shfl_xor_sync(0xffffffffu, v, m);
    __syncthreads();
    if ((threadIdx.x & 31)==0) sh[threadIdx.x>>5] = v;
    __syncthreads();
    return sh[0]+sh[1]+sh[2]+sh[3]+sh[4]+sh[5]+sh[6]+sh[7];
}

// ---------------- LayerNorm (+ optional L2-normalized copy) -----------------
__global__ __launch_bounds__(256) void ln_kernel(const float* __restrict__ X,
        const float* __restrict__ g, const float* __restrict__ b,
        float* __restrict__ O, float* __restrict__ U)
{
    int t = blockIdx.x, tid = threadIdx.x;
    const float* xr = X + t*DIM;
    float v0=xr[tid], v1=xr[tid+256], v2=xr[tid+512];
    float mu  = blockReduceSum256(v0+v1+v2) * (1.0f/DIM);
    float d0=v0-mu, d1=v1-mu, d2=v2-mu;
    float var = blockReduceSum256(d0*d0+d1*d1+d2*d2) * (1.0f/DIM);
    float rstd = rsqrtf(var + 1e-5f);
    float o0 = d0*rstd*g[tid]     + b[tid];
    float o1 = d1*rstd*g[tid+256] + b[tid+256];
    float o2 = d2*rstd*g[tid+512] + b[tid+512];
    float* orow = O + t*DIM;
    orow[tid]=o0; orow[tid+256]=o1; orow[tid+512]=o2;
    if (U){
        float rn = rsqrtf(blockReduceSum256(o0*o0+o1*o1+o2*o2));
        float* ur = U + t*DIM;
        ur[tid]=o0*rn; ur[tid+256]=o1*rn; ur[tid+512]=o2*rn;
    }
}

// ---------------- normalize P rows ------------------------------------------
__global__ __launch_bounds__(256) void pn_kernel(const float* __restrict__ P,
                                                 float* __restrict__ Pn)
{
    int k = blockIdx.x, tid = threadIdx.x;
    const float* pr = P + k*DIM;
    float v0=pr[tid], v1=pr[tid+256], v2=pr[tid+512];
    float rn = rsqrtf(blockReduceSum256(v0*v0+v1*v1+v2*v2));
    float* o = Pn + k*DIM;
    o[tid]=v0*rn; o[tid+256]=v1*rn; o[tid+512]=v2*rn;
}

enum { EPI_NONE=0, EPI_GELU=1, EPI_RES=2 };

// ---------------- small GEMM (64x64 tiles) for N==64 cases ------------------
#define GBK 16
#define GPAD 68
template<int EPI>
__global__ __launch_bounds__(256) void gemm_tn(
        const float* __restrict__ A, const float* __restrict__ W,
        const float* __restrict__ bias, float* __restrict__ C,
        int M, int N, int K,
        const float* __restrict__ R1, const float* __restrict__ R2)
{
    __shared__ float As[GBK][GPAD];   // [k][m]
    __shared__ float Bs[GBK][GPAD];   // [k][n]
    int tid = threadIdx.x;
    int tx = tid & 15, ty = tid >> 4;
    int bm = blockIdx.y * 64, bn = blockIdx.x * 64;
    int lr  = tid >> 2;
    int lk4 = (tid & 3) << 2;
    const float* Ap = A + (bm + lr)*K + lk4;
    const float* Wp = W + (bn + lr)*K + lk4;

    unsigned long long acc[4][2];
    #pragma unroll
    for (int i=0;i<4;i++){ acc[i][0]=0ull; acc[i][1]=0ull; }

    for (int k0=0; k0<K; k0+=GBK){
        float4 av = *reinterpret_cast<const float4*>(Ap + k0);
        float4 wv = *reinterpret_cast<const float4*>(Wp + k0);
        __syncthreads();
        As[lk4+0][lr]=av.x; As[lk4+1][lr]=av.y; As[lk4+2][lr]=av.z; As[lk4+3][lr]=av.w;
        Bs[lk4+0][lr]=wv.x; Bs[lk4+1][lr]=wv.y; Bs[lk4+2][lr]=wv.z; Bs[lk4+3][lr]=wv.w;
        __syncthreads();
        #pragma unroll
        for (int kk=0; kk<GBK; kk++){
            float4 af = *reinterpret_cast<const float4*>(&As[kk][ty<<2]);
            ulonglong2 bf = *reinterpret_cast<const ulonglong2*>(&Bs[kk][tx<<2]);
            unsigned long long a0=pk2(af.x,af.x), a1=pk2(af.y,af.y);
            unsigned long long a2=pk2(af.z,af.z), a3=pk2(af.w,af.w);
            fma2(acc[0][0],a0,bf.x); fma2(acc[0][1],a0,bf.y);
            fma2(acc[1][0],a1,bf.x); fma2(acc[1][1],a1,bf.y);
            fma2(acc[2][0],a2,bf.x); fma2(acc[2][1],a2,bf.y);
            fma2(acc[3][0],a3,bf.x); fma2(acc[3][1],a3,bf.y);
        }
    }

    #pragma unroll
    for (int i=0;i<4;i++){
        int row = bm + (ty<<2) + i;
        #pragma unroll
        for (int p=0;p<2;p++){
            float2 cv = upk(acc[i][p]);
            int col = bn + (tx<<2) + (p<<1);
            float r0 = cv.x, r1 = cv.y;
            if (bias){ r0 += bias[col]; r1 += bias[col+1]; }
            int idx = row*N + col;
            if (EPI==EPI_GELU){ r0 = gelu_f(r0); r1 = gelu_f(r1); }
            else if (EPI==EPI_RES){
                r0 += R1[idx]; r1 += R1[idx+1];
                if (R2){ r0 += R2[idx]; r1 += R2[idx+1]; }
            }
            *reinterpret_cast<float2*>(&C[idx]) = make_float2(r0, r1);
        }
    }
}

// ---------------- main GEMM: 128x128 tile, BK=16, 8x8 per thread ------------
// Double-buffered smem: one __syncthreads per K-iter, LDG latency hidden
// under the compute of the current buffer.
#define BPAD 132
template<int EPI>
__global__ __launch_bounds__(256,2) void gemm128(
        const float* __restrict__ A, const float* __restrict__ W,
        const float* __restrict__ bias, float* __restrict__ C,
        int M, int N, int K,
        const float* __restrict__ R1, const float* __restrict__ R2)
{
    __shared__ float As[2][16][BPAD];   // [buf][k][m]
    __shared__ float Bs[2][16][BPAD];   // [buf][k][n]
    int tid = threadIdx.x;
    int tx = tid & 15, ty = tid >> 4;
    int bm = blockIdx.y * 128, bn = blockIdx.x * 128;
    int lr = tid >> 1;               // 0..127
    int hf = (tid & 1) << 3;         // 0 or 8
    const float* Ap = A + (bm + lr)*K + hf;
    const float* Wp = W + (bn + lr)*K + hf;

    unsigned long long acc[4][8];
    #pragma unroll
    for (int i=0;i<4;i++)
        #pragma unroll
        for (int c=0;c<8;c++) acc[i][c]=0ull;

    // preload tile 0 into buffer 0
    {
        float4 ra0 = *reinterpret_cast<const float4*>(Ap);
        float4 ra1 = *reinterpret_cast<const float4*>(Ap+4);
        float4 rb0 = *reinterpret_cast<const float4*>(Wp);
        float4 rb1 = *reinterpret_cast<const float4*>(Wp+4);
        As[0][hf+0][lr]=ra0.x; As[0][hf+1][lr]=ra0.y; As[0][hf+2][lr]=ra0.z; As[0][hf+3][lr]=ra0.w;
        As[0][hf+4][lr]=ra1.x; As[0][hf+5][lr]=ra1.y; As[0][hf+6][lr]=ra1.z; As[0][hf+7][lr]=ra1.w;
        Bs[0][hf+0][lr]=rb0.x; Bs[0][hf+1][lr]=rb0.y; Bs[0][hf+2][lr]=rb0.z; Bs[0][hf+3][lr]=rb0.w;
        Bs[0][hf+4][lr]=rb1.x; Bs[0][hf+5][lr]=rb1.y; Bs[0][hf+6][lr]=rb1.z; Bs[0][hf+7][lr]=rb1.w;
    }
    __syncthreads();

    int cur = 0;
    for (int k0=0; k0<K; k0+=16){
        bool more = (k0 + 16 < K);
        float4 ra0, ra1, rb0, rb1;
        if (more){
            ra0 = *reinterpret_cast<const float4*>(Ap + k0+16);
            ra1 = *reinterpret_cast<const float4*>(Ap + k0+20);
            rb0 = *reinterpret_cast<const float4*>(Wp + k0+16);
            rb1 = *reinterpret_cast<const float4*>(Wp + k0+20);
        }
        #pragma unroll
        for (int kk=0; kk<16; kk++){
            const float* ar = &As[cur][kk][ty<<3];
            ulonglong2 aA = *reinterpret_cast<const ulonglong2*>(ar);
            ulonglong2 aB = *reinterpret_cast<const ulonglong2*>(ar+4);
            const float* br = &Bs[cur][kk][tx<<3];
            float4 b0 = *reinterpret_cast<const float4*>(br);
            float4 b1 = *reinterpret_cast<const float4*>(br+4);
            unsigned long long bb0=pk2(b0.x,b0.x), bb1=pk2(b0.y,b0.y);
            unsigned long long bb2=pk2(b0.z,b0.z), bb3=pk2(b0.w,b0.w);
            unsigned long long bb4=pk2(b1.x,b1.x), bb5=pk2(b1.y,b1.y);
            unsigned long long bb6=pk2(b1.z,b1.z), bb7=pk2(b1.w,b1.w);
            fma2(acc[0][0],aA.x,bb0); fma2(acc[0][1],aA.x,bb1);
            fma2(acc[0][2],aA.x,bb2); fma2(acc[0][3],aA.x,bb3);
            fma2(acc[0][4],aA.x,bb4); fma2(acc[0][5],aA.x,bb5);
            fma2(acc[0][6],aA.x,bb6); fma2(acc[0][7],aA.x,bb7);
            fma2(acc[1][0],aA.y,bb0); fma2(acc[1][1],aA.y,bb1);
            fma2(acc[1][2],aA.y,bb2); fma2(acc[1][3],aA.y,bb3);
            fma2(acc[1][4],aA.y,bb4); fma2(acc[1][5],aA.y,bb5);
            fma2(acc[1][6],aA.y,bb6); fma2(acc[1][7],aA.y,bb7);
            fma2(acc[2][0],aB.x,bb0); fma2(acc[2][1],aB.x,bb1);
            fma2(acc[2][2],aB.x,bb2); fma2(acc[2][3],aB.x,bb3);
            fma2(acc[2][4],aB.x,bb4); fma2(acc[2][5],aB.x,bb5);
            fma2(acc[2][6],aB.x,bb6); fma2(acc[2][7],aB.x,bb7);
            fma2(acc[3][0],aB.y,bb0); fma2(acc[3][1],aB.y,bb1);
            fma2(acc[3][2],aB.y,bb2); fma2(acc[3][3],aB.y,bb3);
            fma2(acc[3][4],aB.y,bb4); fma2(acc[3][5],aB.y,bb5);
            fma2(acc[3][6],aB.y,bb6); fma2(acc[3][7],aB.y,bb7);
        }
        if (more){
            int nxt = cur ^ 1;
            As[nxt][hf+0][lr]=ra0.x; As[nxt][hf+1][lr]=ra0.y; As[nxt][hf+2][lr]=ra0.z; As[nxt][hf+3][lr]=ra0.w;
            As[nxt][hf+4][lr]=ra1.x; As[nxt][hf+5][lr]=ra1.y; As[nxt][hf+6][lr]=ra1.z; As[nxt][hf+7][lr]=ra1.w;
            Bs[nxt][hf+0][lr]=rb0.x; Bs[nxt][hf+1][lr]=rb0.y; Bs[nxt][hf+2][lr]=rb0.z; Bs[nxt][hf+3][lr]=rb0.w;
            Bs[nxt][hf+4][lr]=rb1.x; Bs[nxt][hf+5][lr]=rb1.y; Bs[nxt][hf+6][lr]=rb1.z; Bs[nxt][hf+7][lr]=rb1.w;
            __syncthreads();
            cur = nxt;
        }
    }

    // epilogue: acc[rp][c] = rows (ty*8+2rp, +1), col tx*8+c
    float bsv[8];
    #pragma unroll
    for (int c=0;c<8;c++) bsv[c] = bias ? bias[bn + (tx<<3) + c] : 0.0f;

    #pragma unroll
    for (int rp=0;rp<4;rp++){
        #pragma unroll
        for (int p=0;p<2;p++){
            int row = bm + (ty<<3) + rp*2 + p;
            float v[8];
            #pragma unroll
            for (int c=0;c<8;c++){
                float2 t = upk(acc[rp][c]);
                v[c] = (p ? t.y : t.x) + bsv[c];
            }
            int idx = row*N + bn + (tx<<3);
            if (EPI==EPI_GELU){
                #pragma unroll
                for (int c=0;c<8;c++) v[c] = gelu_f(v[c]);
            } else if (EPI==EPI_RES){
                #pragma unroll
                for (int c=0;c<8;c++) v[c] += R1[idx+c];
                if (R2){
                    #pragma unroll
                    for (int c=0;c<8;c++) v[c] += R2[idx+c];
                }
            }
            *reinterpret_cast<float4*>(&C[idx])   = make_float4(v[0],v[1],v[2],v[3]);
            *reinterpret_cast<float4*>(&C[idx+4]) = make_float4(v[4],v[5],v[6],v[7]);
        }
    }
}

// ---------------- fused flash attention: 128q x 64kv tiles ------------------
// grid (SEQ/128, BATCH*NH), 256 threads. Per thread: 8q x 4k (S) / 8q x 4d (O).
// smem: Qt[d][q] s132, Kt[d][k] s68 (aliased by Pt[k][q] s140), Vs[k][d] s68.
#define QT_S 132
#define KT_S 68
#define PT_S 140
#define VS_S 68
#define ATTN_SMEM2 ((64*QT_S + 64*PT_S + 64*VS_S)*4)   // 87040 B

__global__ __launch_bounds__(256,2) void attn_kernel(const float* __restrict__ qkv,
                                                     float* __restrict__ out)
{
    extern __shared__ float sm[];
    float* Qt = sm;                    // 64 x 132
    float* Kt = sm + 64*QT_S;          // 64 x 68 (inside 64x140 region)
    float* Pt = Kt;                    // 64 x 140 (alias)
    float* Vs = sm + 64*QT_S + 64*PT_S;// 64 x 68

    int tid = threadIdx.x;
    int tx = tid & 15, ty = tid >> 4;
    int b = blockIdx.y / NH, h = blockIdx.y % NH;
    int q0 = blockIdx.x * 128;
    const float* base = qkv + b*SEQ*3*DIM;

    {   // load Q tile transposed (128 rows x 64 d)
        int lr = tid >> 1, dh = (tid & 1) * 32;
        const float* qp = base + (q0+lr)*3*DIM + h*HD + dh;
        #pragma unroll
        for (int u=0; u<8; u++){
            float4 qv = *reinterpret_cast<const float4*>(qp + u*4);
            int dc = dh + u*4;
            Qt[(dc+0)*QT_S+lr]=qv.x; Qt[(dc+1)*QT_S+lr]=qv.y;
            Qt[(dc+2)*QT_S+lr]=qv.z; Qt[(dc+3)*QT_S+lr]=qv.w;
        }
    }

    float m_i[8], l_i[8];
    unsigned long long o2[4][4];
    #pragma unroll
    for (int i=0;i<8;i++){ m_i[i]=-INFINITY; l_i[i]=0.f; }
    #pragma unroll
    for (int i=0;i<4;i++)
        #pragma unroll
        for (int c=0;c<4;c++) o2[i][c]=0ull;

    int lr4 = tid >> 2, dq = (tid & 3) * 16;

    for (int j=0; j<SEQ/64; j++){
        const float* kp = base + (j*64+lr4)*3*DIM + DIM + h*HD + dq;
        float4 kreg[4], vreg[4];
        #pragma unroll
        for (int u=0; u<4; u++){
            kreg[u] = *reinterpret_cast<const float4*>(kp + u*4);
            vreg[u] = *reinterpret_cast<const float4*>(kp + DIM + u*4);
        }
        __syncthreads();   // prior PV readers (Pt/Vs) done
        #pragma unroll
        for (int u=0; u<4; u++){
            int dc = dq + u*4;
            Kt[(dc+0)*KT_S+lr4]=kreg[u].x; Kt[(dc+1)*KT_S+lr4]=kreg[u].y;
            Kt[(dc+2)*KT_S+lr4]=kreg[u].z; Kt[(dc+3)*KT_S+lr4]=kreg[u].w;
            *reinterpret_cast<float4*>(&Vs[lr4*VS_S + dc]) = vreg[u];
        }
        __syncthreads();

        // S = Q K^T : 8q x 4k per thread (q pairs in fp32x2)
        unsigned long long s2[4][4];
        #pragma unroll
        for (int i=0;i<4;i++)
            #pragma unroll
            for (int c=0;c<4;c++) s2[i][c]=0ull;
        #pragma unroll 8
        for (int d=0; d<HD; d++){
            const float* qr_ = &Qt[d*QT_S + (ty<<3)];
            ulonglong2 qa = *reinterpret_cast<const ulonglong2*>(qr_);
            ulonglong2 qb = *reinterpret_cast<const ulonglong2*>(qr_+4);
            float4 kv = *reinterpret_cast<const float4*>(&Kt[d*KT_S + (tx<<2)]);
            unsigned long long k0=pk2(kv.x,kv.x), k1=pk2(kv.y,kv.y);
            unsigned long long k2=pk2(kv.z,kv.z), k3=pk2(kv.w,kv.w);
            fma2(s2[0][0],qa.x,k0); fma2(s2[0][1],qa.x,k1);
            fma2(s2[0][2],qa.x,k2); fma2(s2[0][3],qa.x,k3);
            fma2(s2[1][0],qa.y,k0); fma2(s2[1][1],qa.y,k1);
            fma2(s2[1][2],qa.y,k2); fma2(s2[1][3],qa.y,k3);
            fma2(s2[2][0],qb.x,k0); fma2(s2[2][1],qb.x,k1);
            fma2(s2[2][2],qb.x,k2); fma2(s2[2][3],qb.x,k3);
            fma2(s2[3][0],qb.y,k0); fma2(s2[3][1],qb.y,k1);
            fma2(s2[3][2],qb.y,k2); fma2(s2[3][3],qb.y,k3);
        }

        // online softmax over 64-wide rows (16 tx lanes x 4 each)
        float p[8][4];
        #pragma unroll
        for (int rp=0;rp<4;rp++)
            #pragma unroll
            for (int c=0;c<4;c++){
                float2 t = upk(s2[rp][c]);
                p[2*rp  ][c] = t.x*0.125f;
                p[2*rp+1][c] = t.y*0.125f;
            }
        float cf[8];
        #pragma unroll
        for (int qr=0;qr<8;qr++){
            float mx = fmaxf(fmaxf(p[qr][0],p[qr][1]), fmaxf(p[qr][2],p[qr][3]));
            #pragma unroll
            for (int m=8;m>0;m>>=1) mx = fmaxf(mx, __shfl_xor_sync(0xffffffffu, mx, m));
            float mn = fmaxf(m_i[qr], mx);
            cf[qr] = __expf(m_i[qr] - mn);
            m_i[qr] = mn;
            float s = 0.f;
            #pragma unroll
            for (int c=0;c<4;c++){ p[qr][c] = __expf(p[qr][c]-mn); s += p[qr][c]; }
            #pragma unroll
            for (int m=8;m>0;m>>=1) s += __shfl_xor_sync(0xffffffffu, s, m);
            l_i[qr] = l_i[qr]*cf[qr] + s;
        }
        #pragma unroll
        for (int rp=0;rp<4;rp++){
            unsigned long long c2 = pk2(cf[2*rp], cf[2*rp+1]);
            mul2(o2[rp][0],c2); mul2(o2[rp][1],c2);
            mul2(o2[rp][2],c2); mul2(o2[rp][3],c2);
        }
        __syncthreads();   // Kt readers done before Pt (=Kt region) writes
        #pragma unroll
        for (int c=0;c<4;c++)
            #pragma unroll
            for (int rp=0;rp<4;rp++)
                *reinterpret_cast<unsigned long long*>(
                    &Pt[((tx<<2)+c)*PT_S + (ty<<3) + rp*2]) = pk2(p[2*rp][c], p[2*rp+1][c]);
        __syncthreads();

        // O += P V : 8q x 4d per thread
        #pragma unroll 8
        for (int kj=0; kj<64; kj++){
            const float* pr = &Pt[kj*PT_S + (ty<<3)];
            ulonglong2 pa = *reinterpret_cast<const ulonglong2*>(pr);
            ulonglong2 pb = *reinterpret_cast<const ulonglong2*>(pr+4);
            float4 vv = *reinterpret_cast<const float4*>(&Vs[kj*VS_S + (tx<<2)]);
            unsigned long long v0=pk2(vv.x,vv.x), v1=pk2(vv.y,vv.y);
            unsigned long long v2=pk2(vv.z,vv.z), v3=pk2(vv.w,vv.w);
            fma2(o2[0][0],pa.x,v0); fma2(o2[0][1],pa.x,v1);
            fma2(o2[0][2],pa.x,v2); fma2(o2[0][3],pa.x,v3);
            fma2(o2[1][0],pa.y,v0); fma2(o2[1][1],pa.y,v1);
            fma2(o2[1][2],pa.y,v2); fma2(o2[1][3],pa.y,v3);
            fma2(o2[2][0],pb.x,v0); fma2(o2[2][1],pb.x,v1);
            fma2(o2[2][2],pb.x,v2); fma2(o2[2][3],pb.x,v3);
            fma2(o2[3][0],pb.y,v0); fma2(o2[3][1],pb.y,v1);
            fma2(o2[3][2],pb.y,v2); fma2(o2[3][3],pb.y,v3);
        }
    }

    #pragma unroll
    for (int rp=0;rp<4;rp++){
        #pragma unroll
        for (int p=0;p<2;p++){
            int qr = rp*2 + p;
            float inv = 1.0f / l_i[qr];
            int row = b*SEQ + q0 + (ty<<3) + qr;
            float2 t0 = upk(o2[rp][0]); float2 t1 = upk(o2[rp][1]);
            float2 t2 = upk(o2[rp][2]); float2 t3 = upk(o2[rp][3]);
            float4 ov;
            ov.x = (p ? t0.y : t0.x) * inv;
            ov.y = (p ? t1.y : t1.x) * inv;
            ov.z = (p ? t2.y : t2.x) * inv;
            ov.w = (p ? t3.y : t3.x) * inv;
            *reinterpret_cast<float4*>(&out[row*DIM + h*HD + (tx<<2)]) = ov;
        }
    }
}

// ---------------- launch -----------------------------------------------------
extern "C" void kernel_launch(void* const* d_in, const int* in_sizes, int n_in,
                              void* d_out, int out_size)
{
    const float* x     =(const float*)d_in[0];
    const float* ln1g  =(const float*)d_in[1];
    const float* ln1b  =(const float*)d_in[2];
    const float* qkvw  =(const float*)d_in[3];
    const float* qkvbi =(const float*)d_in[4];
    const float* projw =(const float*)d_in[5];
    const float* projb =(const float*)d_in[6];
    const float* cqkvw =(const float*)d_in[7];
    const float* cqkvb =(const float*)d_in[8];
    const float* cprojw=(const float*)d_in[9];
    const float* cprojb=(const float*)d_in[10];
    const float* cf1w  =(const float*)d_in[11];
    const float* cf1b  =(const float*)d_in[12];
    const float* cf2w  =(const float*)d_in[13];
    const float* cf2b  =(const float*)d_in[14];
    const float* P     =(const float*)d_in[15];
    const float* ln2g  =(const float*)d_in[16];
    const float* ln2b  =(const float*)d_in[17];
    const float* f1w   =(const float*)d_in[18];
    const float* f1b   =(const float*)d_in[19];
    const float* f2w   =(const float*)d_in[20];
    const float* f2b   =(const float*)d_in[21];

    float *n1,*un,*qkvb,*ao,*y,*cph,*zin,*xa,*n2,*hid,*Pn;
    cudaGetSymbolAddress((void**)&n1,  g_n1);
    cudaGetSymbolAddress((void**)&un,  g_un);
    cudaGetSymbolAddress((void**)&qkvb,g_qkv);
    cudaGetSymbolAddress((void**)&ao,  g_ao);
    cudaGetSymbolAddress((void**)&y,   g_y);
    cudaGetSymbolAddress((void**)&cph, g_cph);
    cudaGetSymbolAddress((void**)&zin, g_zin);
    cudaGetSymbolAddress((void**)&xa,  g_xa);
    cudaGetSymbolAddress((void**)&n2,  g_n2);
    cudaGetSymbolAddress((void**)&hid, g_hid);
    cudaGetSymbolAddress((void**)&Pn,  g_Pn);

    float* outx = (float*)d_out;
    float* dmap = outx + X_ELEMS;

    cudaFuncSetAttribute(attn_kernel,
        cudaFuncAttributeMaxDynamicSharedMemorySize, ATTN_SMEM2);

    // Pn = normalize(P)
    pn_kernel<<<KP,256>>>(P, Pn);
    // n1 = LN1(x), un = n1/||n1||
    ln_kernel<<<NTOK,256>>>(x, ln1g, ln1b, n1, un);
    // qkv = n1 @ qkv_w^T + b
    gemm128<EPI_NONE><<<dim3(18,64),256>>>(n1, qkvw, qkvbi, qkvb, NTOK, 3*DIM, DIM, 0, 0);
    // attention 1
    attn_kernel<<<dim3(SEQ/128, BATCH*NH),256,ATTN_SMEM2>>>(qkvb, ao);
    // y = ao @ proj_w^T + b
    gemm128<EPI_NONE><<<dim3(6,64),256>>>(ao, projw, projb, y, NTOK, DIM, DIM, 0, 0);
    // dmap = un @ Pn^T   (second output, N=64)
    gemm_tn<EPI_NONE><<<dim3(1,128),256>>>(un, Pn, (const float*)0, dmap, NTOK, KP, DIM, 0, 0);
    // c_project MLP: cph = gelu(dmap @ cf1^T + b); zin = cph @ cf2^T + b
    gemm_tn<EPI_GELU><<<dim3(1,128),256>>>(dmap, cf1w, cf1b, cph, NTOK, KP, KP, 0, 0);
    gemm128<EPI_NONE><<<dim3(6,64),256>>>(cph, cf2w, cf2b, zin, NTOK, DIM, KP, 0, 0);
    // qkv2 = zin @ c_qkv^T + b
    gemm128<EPI_NONE><<<dim3(18,64),256>>>(zin, cqkvw, cqkvb, qkvb, NTOK, 3*DIM, DIM, 0, 0);
    // attention 2
    attn_kernel<<<dim3(SEQ/128, BATCH*NH),256,ATTN_SMEM2>>>(qkvb, ao);
    // xa = ao @ c_proj^T + b + x + y
    gemm128<EPI_RES><<<dim3(6,64),256>>>(ao, cprojw, cprojb, xa, NTOK, DIM, DIM, x, y);
    // n2 = LN2(xa)
    ln_kernel<<<NTOK,256>>>(xa, ln2g, ln2b, n2, (float*)0);
    // hid = gelu(n2 @ fc1^T + b)
    gemm128<EPI_GELU><<<dim3(24,64),256>>>(n2, f1w, f1b, hid, NTOK, MLPH, DIM, 0, 0);
    // out_x = hid @ fc2^T + b + xa
    gemm128<EPI_RES><<<dim3(6,64),256>>>(hid, f2w, f2b, outx, NTOK, DIM, MLPH, xa, 0);
}

// round 14
// speedup vs baseline: 1.6896x; 1.6896x over previous
#include <cuda_runtime.h>
#include <cuda_bf16.h>
#include <math.h>
#include <stdint.h>

#define DIM   768
#define SEQ   1024
#define BATCH 8
#define NTOK  (BATCH*SEQ)      // 8192
#define NH    12
#define HD    64
#define KP    64
#define MLPH  3072
#define X_ELEMS (NTOK*DIM)     // 6291456

// ---------------- scratch (device globals; no allocation allowed) ----------
__device__ float g_n1 [NTOK*DIM];
__device__ float g_un [NTOK*DIM];
__device__ float g_qkv[NTOK*3*DIM];
__device__ float g_ao [NTOK*DIM];
__device__ float g_y  [NTOK*DIM];
__device__ float g_cph[NTOK*KP];
__device__ float g_zin[NTOK*DIM];
__device__ float g_xa [NTOK*DIM];
__device__ float g_n2 [NTOK*DIM];
__device__ float g_hid[NTOK*MLPH];
__device__ float g_Pn [KP*DIM];
// bf16 split buffers (A: up to NTOK*MLPH; W: up to MLPH*DIM)
__device__ __nv_bfloat16 g_Ahi[NTOK*MLPH];
__device__ __nv_bfloat16 g_Alo[NTOK*MLPH];
__device__ __nv_bfloat16 g_Whi[MLPH*DIM];
__device__ __nv_bfloat16 g_Wlo[MLPH*DIM];

// ---------------- packed fp32x2 helpers (sm_103a FFMA2) --------------------
__device__ __forceinline__ unsigned long long pk2(float lo, float hi){
    unsigned long long r;
    asm("mov.b64 %0, {%1, %2};" : "=l"(r) : "f"(lo), "f"(hi));
    return r;
}
__device__ __forceinline__ void fma2(unsigned long long& d,
                                     unsigned long long a, unsigned long long b){
    asm("fma.rn.f32x2 %0, %1, %2, %0;" : "+l"(d) : "l"(a), "l"(b));
}
__device__ __forceinline__ void mul2(unsigned long long& d, unsigned long long a){
    asm("mul.rn.f32x2 %0, %0, %1;" : "+l"(d) : "l"(a));
}
__device__ __forceinline__ float2 upk(unsigned long long v){
    float2 r;
    asm("mov.b64 {%0, %1}, %2;" : "=f"(r.x), "=f"(r.y) : "l"(v));
    return r;
}
__device__ __forceinline__ float gelu_f(float x){
    return 0.5f*x*(1.0f + erff(x*0.70710678118654752440f));
}

// ---------------- warp-MMA helpers (baseline PTX, sm_80-era) ----------------
__device__ __forceinline__ uint32_t smem_u32_of(const void* p){
    uint32_t a;
    asm("{ .reg .u64 t; cvta.to.shared.u64 t, %1; cvt.u32.u64 %0, t; }"
        : "=r"(a) : "l"(p));
    return a;
}
__device__ __forceinline__ void ldsm4(uint32_t addr, uint32_t* r){
    asm volatile("ldmatrix.sync.aligned.m8n8.x4.shared.b16 {%0,%1,%2,%3}, [%4];"
        : "=r"(r[0]), "=r"(r[1]), "=r"(r[2]), "=r"(r[3]) : "r"(addr));
}
__device__ __forceinline__ void mma_bf16(float* d, const uint32_t* a,
                                         uint32_t b0, uint32_t b1){
    asm volatile("mma.sync.aligned.m16n8k16.row.col.f32.bf16.bf16.f32 "
        "{%0,%1,%2,%3}, {%4,%5,%6,%7}, {%8,%9}, {%0,%1,%2,%3};"
        : "+f"(d[0]), "+f"(d[1]), "+f"(d[2]), "+f"(d[3])
        : "r"(a[0]), "r"(a[1]), "r"(a[2]), "r"(a[3]), "r"(b0), "r"(b1));
}

// ---------------- block reduction (256 threads) -----------------------------
__device__ __forceinline__ float blockReduceSum256(float v){
    __shared__ float sh[8];
    #pragma unroll
    for (int m=16; m>0; m>>=1) v += __shfl_xor_sync(0xffffffffu, v, m);
    __syncthreads();
    if ((threadIdx.x & 31)==0) sh[threadIdx.x>>5] = v;
    __syncthreads();
    return sh[0]+sh[1]+sh[2]+sh[3]+sh[4]+sh[5]+sh[6]+sh[7];
}

// ---------------- LayerNorm (+ optional L2-normalized copy) -----------------
__global__ __launch_bounds__(256) void ln_kernel(const float* __restrict__ X,
        const float* __restrict__ g, const float* __restrict__ b,
        float* __restrict__ O, float* __restrict__ U)
{
    int t = blockIdx.x, tid = threadIdx.x;
    const float* xr = X + t*DIM;
    float v0=xr[tid], v1=xr[tid+256], v2=xr[tid+512];
    float mu  = blockReduceSum256(v0+v1+v2) * (1.0f/DIM);
    float d0=v0-mu, d1=v1-mu, d2=v2-mu;
    float var = blockReduceSum256(d0*d0+d1*d1+d2*d2) * (1.0f/DIM);
    float rstd = rsqrtf(var + 1e-5f);
    float o0 = d0*rstd*g[tid]     + b[tid];
    float o1 = d1*rstd*g[tid+256] + b[tid+256];
    float o2 = d2*rstd*g[tid+512] + b[tid+512];
    float* orow = O + t*DIM;
    orow[tid]=o0; orow[tid+256]=o1; orow[tid+512]=o2;
    if (U){
        float rn = rsqrtf(blockReduceSum256(o0*o0+o1*o1+o2*o2));
        float* ur = U + t*DIM;
        ur[tid]=o0*rn; ur[tid+256]=o1*rn; ur[tid+512]=o2*rn;
    }
}

// ---------------- normalize P rows ------------------------------------------
__global__ __launch_bounds__(256) void pn_kernel(const float* __restrict__ P,
                                                 float* __restrict__ Pn)
{
    int k = blockIdx.x, tid = threadIdx.x;
    const float* pr = P + k*DIM;
    float v0=pr[tid], v1=pr[tid+256], v2=pr[tid+512];
    float rn = rsqrtf(blockReduceSum256(v0*v0+v1*v1+v2*v2));
    float* o = Pn + k*DIM;
    o[tid]=v0*rn; o[tid+256]=v1*rn; o[tid+512]=v2*rn;
}

// ---------------- fp32 -> bf16 hi/lo split ----------------------------------
__global__ __launch_bounds__(256) void cvt_split(const float* __restrict__ X,
        __nv_bfloat16* __restrict__ hi, __nv_bfloat16* __restrict__ lo, int n4)
{
    const float4* X4 = reinterpret_cast<const float4*>(X);
    uint2* H = reinterpret_cast<uint2*>(hi);
    uint2* L = reinterpret_cast<uint2*>(lo);
    int stride = gridDim.x * 256;
    for (int i = blockIdx.x*256 + threadIdx.x; i < n4; i += stride){
        float4 v = X4[i];
        __nv_bfloat16 h0=__float2bfloat16(v.x), h1=__float2bfloat16(v.y);
        __nv_bfloat16 h2=__float2bfloat16(v.z), h3=__float2bfloat16(v.w);
        __nv_bfloat16 l0=__float2bfloat16(v.x-__bfloat162float(h0));
        __nv_bfloat16 l1=__float2bfloat16(v.y-__bfloat162float(h1));
        __nv_bfloat16 l2=__float2bfloat16(v.z-__bfloat162float(h2));
        __nv_bfloat16 l3=__float2bfloat16(v.w-__bfloat162float(h3));
        uint2 ho, lv;
        ho.x = (uint32_t)__bfloat16_as_ushort(h0) | ((uint32_t)__bfloat16_as_ushort(h1)<<16);
        ho.y = (uint32_t)__bfloat16_as_ushort(h2) | ((uint32_t)__bfloat16_as_ushort(h3)<<16);
        lv.x = (uint32_t)__bfloat16_as_ushort(l0) | ((uint32_t)__bfloat16_as_ushort(l1)<<16);
        lv.y = (uint32_t)__bfloat16_as_ushort(l2) | ((uint32_t)__bfloat16_as_ushort(l3)<<16);
        H[i] = ho; L[i] = lv;
    }
}

enum { EPI_NONE=0, EPI_GELU=1, EPI_RES=2 };

// ---------------- small GEMM (64x64 tiles) for N==64 cases ------------------
#define GBK 16
#define GPAD 68
template<int EPI>
__global__ __launch_bounds__(256) void gemm_tn(
        const float* __restrict__ A, const float* __restrict__ W,
        const float* __restrict__ bias, float* __restrict__ C,
        int M, int N, int K,
        const float* __restrict__ R1, const float* __restrict__ R2)
{
    __shared__ float As[GBK][GPAD];
    __shared__ float Bs[GBK][GPAD];
    int tid = threadIdx.x;
    int tx = tid & 15, ty = tid >> 4;
    int bm = blockIdx.y * 64, bn = blockIdx.x * 64;
    int lr  = tid >> 2;
    int lk4 = (tid & 3) << 2;
    const float* Ap = A + (bm + lr)*K + lk4;
    const float* Wp = W + (bn + lr)*K + lk4;

    unsigned long long acc[4][2];
    #pragma unroll
    for (int i=0;i<4;i++){ acc[i][0]=0ull; acc[i][1]=0ull; }

    for (int k0=0; k0<K; k0+=GBK){
        float4 av = *reinterpret_cast<const float4*>(Ap + k0);
        float4 wv = *reinterpret_cast<const float4*>(Wp + k0);
        __syncthreads();
        As[lk4+0][lr]=av.x; As[lk4+1][lr]=av.y; As[lk4+2][lr]=av.z; As[lk4+3][lr]=av.w;
        Bs[lk4+0][lr]=wv.x; Bs[lk4+1][lr]=wv.y; Bs[lk4+2][lr]=wv.z; Bs[lk4+3][lr]=wv.w;
        __syncthreads();
        #pragma unroll
        for (int kk=0; kk<GBK; kk++){
            float4 af = *reinterpret_cast<const float4*>(&As[kk][ty<<2]);
            ulonglong2 bf = *reinterpret_cast<const ulonglong2*>(&Bs[kk][tx<<2]);
            unsigned long long a0=pk2(af.x,af.x), a1=pk2(af.y,af.y);
            unsigned long long a2=pk2(af.z,af.z), a3=pk2(af.w,af.w);
            fma2(acc[0][0],a0,bf.x); fma2(acc[0][1],a0,bf.y);
            fma2(acc[1][0],a1,bf.x); fma2(acc[1][1],a1,bf.y);
            fma2(acc[2][0],a2,bf.x); fma2(acc[2][1],a2,bf.y);
            fma2(acc[3][0],a3,bf.x); fma2(acc[3][1],a3,bf.y);
        }
    }

    #pragma unroll
    for (int i=0;i<4;i++){
        int row = bm + (ty<<2) + i;
        #pragma unroll
        for (int p=0;p<2;p++){
            float2 cv = upk(acc[i][p]);
            int col = bn + (tx<<2) + (p<<1);
            float r0 = cv.x, r1 = cv.y;
            if (bias){ r0 += bias[col]; r1 += bias[col+1]; }
            int idx = row*N + col;
            if (EPI==EPI_GELU){ r0 = gelu_f(r0); r1 = gelu_f(r1); }
            else if (EPI==EPI_RES){
                r0 += R1[idx]; r1 += R1[idx+1];
                if (R2){ r0 += R2[idx]; r1 += R2[idx+1]; }
            }
            *reinterpret_cast<float2*>(&C[idx]) = make_float2(r0, r1);
        }
    }
}

// ---------------- tensor-core GEMM via mma.sync (bf16x3 split) ---------------
// C[m][n] = sum_k A[m][k]*W[n][k] (+epi). CTA tile 128x128, BK=32, 8 warps
// as 2(m) x 4(n), warp tile 64x32. Frags via ldmatrix.x4, HMMA m16n8k16.
// smem stride 40 bf16 (80 B): 8-row LDSM pointer sets hit distinct 16B groups.
#define MSA 40
template<int EPI>
__global__ __launch_bounds__(256) void gemm_mma(
        const __nv_bfloat16* __restrict__ Ahi, const __nv_bfloat16* __restrict__ Alo,
        const __nv_bfloat16* __restrict__ Whi, const __nv_bfloat16* __restrict__ Wlo,
        const float* __restrict__ bias, float* __restrict__ C,
        int M, int N, int K,
        const float* __restrict__ R1, const float* __restrict__ R2)
{
    __shared__ __nv_bfloat16 sAhi[128*MSA];
    __shared__ __nv_bfloat16 sAlo[128*MSA];
    __shared__ __nv_bfloat16 sWhi[128*MSA];
    __shared__ __nv_bfloat16 sWlo[128*MSA];

    int tid = threadIdx.x, wid = tid>>5, lid = tid&31;
    int wm = wid>>2, wn = wid&3;
    int bm = blockIdx.y*128, bn = blockIdx.x*128;

    float acc[4][4][4];
    #pragma unroll
    for (int a=0;a<4;a++)
        #pragma unroll
        for (int b=0;b<4;b++)
            #pragma unroll
            for (int c=0;c<4;c++) acc[a][b][c]=0.f;

    uint32_t aAhi = smem_u32_of(sAhi), aAlo = smem_u32_of(sAlo);
    uint32_t aWhi = smem_u32_of(sWhi), aWlo = smem_u32_of(sWlo);

    int lrow = tid>>2, lc = tid&3;          // global->smem: 2x(row,16B-chunk)
    int arow = lid & 15, asel = lid >> 4;   // A ldmatrix lane geometry
    int brow = (lid & 7) + ((lid >> 4) << 3), bsel = (lid >> 3) & 1;  // W lanes

    int ns = K >> 5;
    for (int s = 0; s < ns; s++){
        int k0 = s << 5;
        __syncthreads();
        #pragma unroll
        for (int v = 0; v < 2; v++){
            int row = lrow + v*64;
            long ga = (long)(bm + row)*K + k0 + lc*8;
            long gw = (long)(bn + row)*K + k0 + lc*8;
            uint32_t so = (uint32_t)(row*MSA + lc*8)*2u;
            *reinterpret_cast<uint4*>(reinterpret_cast<char*>(sAhi)+so) = *reinterpret_cast<const uint4*>(Ahi + ga);
            *reinterpret_cast<uint4*>(reinterpret_cast<char*>(sAlo)+so) = *reinterpret_cast<const uint4*>(Alo + ga);
            *reinterpret_cast<uint4*>(reinterpret_cast<char*>(sWhi)+so) = *reinterpret_cast<const uint4*>(Whi + gw);
            *reinterpret_cast<uint4*>(reinterpret_cast<char*>(sWlo)+so) = *reinterpret_cast<const uint4*>(Wlo + gw);
        }
        __syncthreads();
        #pragma unroll
        for (int h = 0; h < 2; h++){
            uint32_t ah[4][4], wh[2][4], wl[2][4];
            #pragma unroll
            for (int mf=0; mf<4; mf++){
                uint32_t off = (uint32_t)((wm*64 + mf*16 + arow)*80 + h*32 + asel*16);
                ldsm4(aAhi + off, ah[mf]);
            }
            #pragma unroll
            for (int nf2=0; nf2<2; nf2++){
                uint32_t off = (uint32_t)((wn*32 + nf2*16 + brow)*80 + h*32 + bsel*16);
                ldsm4(aWhi + off, wh[nf2]);
                ldsm4(aWlo + off, wl[nf2]);
            }
            // terms using ah: ah*wh, ah*wl
            #pragma unroll
            for (int mf=0; mf<4; mf++)
                #pragma unroll
                for (int nf=0; nf<4; nf++){
                    mma_bf16(acc[mf][nf], ah[mf], wh[nf>>1][(nf&1)*2], wh[nf>>1][(nf&1)*2+1]);
                    mma_bf16(acc[mf][nf], ah[mf], wl[nf>>1][(nf&1)*2], wl[nf>>1][(nf&1)*2+1]);
                }
            // load al (reuses ah's register space after last use) : al*wh
            uint32_t al[4][4];
            #pragma unroll
            for (int mf=0; mf<4; mf++){
                uint32_t off = (uint32_t)((wm*64 + mf*16 + arow)*80 + h*32 + asel*16);
                ldsm4(aAlo + off, al[mf]);
            }
            #pragma unroll
            for (int mf=0; mf<4; mf++)
                #pragma unroll
                for (int nf=0; nf<4; nf++)
                    mma_bf16(acc[mf][nf], al[mf], wh[nf>>1][(nf&1)*2], wh[nf>>1][(nf&1)*2+1]);
        }
    }

    // epilogue: frag (mf,nf): rows bm+wm*64+mf*16+{tr, tr+8}, cols +tc..tc+1
    int tr = lid >> 2, tc = (lid & 3) * 2;
    #pragma unroll
    for (int mf=0; mf<4; mf++){
        #pragma unroll
        for (int nf=0; nf<4; nf++){
            int row = bm + wm*64 + mf*16 + tr;
            int col = bn + wn*32 + nf*8 + tc;
            float b0 = bias ? bias[col] : 0.f;
            float b1 = bias ? bias[col+1] : 0.f;
            #pragma unroll
            for (int g=0; g<2; g++){
                int r = row + g*8;
                float v0 = acc[mf][nf][g*2+0] + b0;
                float v1 = acc[mf][nf][g*2+1] + b1;
                long idx = (long)r*N + col;
                if (EPI==EPI_GELU){ v0 = gelu_f(v0); v1 = gelu_f(v1); }
                else if (EPI==EPI_RES){
                    float2 r1v = *reinterpret_cast<const float2*>(R1 + idx);
                    v0 += r1v.x; v1 += r1v.y;
                    if (R2){
                        float2 r2v = *reinterpret_cast<const float2*>(R2 + idx);
                        v0 += r2v.x; v1 += r2v.y;
                    }
                }
                *reinterpret_cast<float2*>(C + idx) = make_float2(v0, v1);
            }
        }
    }
}

// ---------------- fused flash attention: 128q x 64kv tiles ------------------
#define QT_S 132
#define KT_S 68
#define PT_S 140
#define VS_S 68
#define ATTN_SMEM2 ((64*QT_S + 64*PT_S + 64*VS_S)*4)   // 87040 B

__global__ __launch_bounds__(256) void attn_kernel(const float* __restrict__ qkv,
                                                   float* __restrict__ out)
{
    extern __shared__ float sm[];
    float* Qt = sm;
    float* Kt = sm + 64*QT_S;
    float* Pt = Kt;
    float* Vs = sm + 64*QT_S + 64*PT_S;

    int tid = threadIdx.x;
    int tx = tid & 15, ty = tid >> 4;
    int b = blockIdx.y / NH, h = blockIdx.y % NH;
    int q0 = blockIdx.x * 128;
    const float* base = qkv + b*SEQ*3*DIM;

    {
        int lr = tid >> 1, dh = (tid & 1) * 32;
        const float* qp = base + (q0+lr)*3*DIM + h*HD + dh;
        #pragma unroll
        for (int u=0; u<8; u++){
            float4 qv = *reinterpret_cast<const float4*>(qp + u*4);
            int dc = dh + u*4;
            Qt[(dc+0)*QT_S+lr]=qv.x; Qt[(dc+1)*QT_S+lr]=qv.y;
            Qt[(dc+2)*QT_S+lr]=qv.z; Qt[(dc+3)*QT_S+lr]=qv.w;
        }
    }

    float m_i[8], l_i[8];
    unsigned long long o2[4][4];
    #pragma unroll
    for (int i=0;i<8;i++){ m_i[i]=-INFINITY; l_i[i]=0.f; }
    #pragma unroll
    for (int i=0;i<4;i++)
        #pragma unroll
        for (int c=0;c<4;c++) o2[i][c]=0ull;

    int lr4 = tid >> 2, dq = (tid & 3) * 16;

    for (int j=0; j<SEQ/64; j++){
        const float* kp = base + (j*64+lr4)*3*DIM + DIM + h*HD + dq;
        float4 kreg[4], vreg[4];
        #pragma unroll
        for (int u=0; u<4; u++){
            kreg[u] = *reinterpret_cast<const float4*>(kp + u*4);
            vreg[u] = *reinterpret_cast<const float4*>(kp + DIM + u*4);
        }
        __syncthreads();
        #pragma unroll
        for (int u=0; u<4; u++){
            int dc = dq + u*4;
            Kt[(dc+0)*KT_S+lr4]=kreg[u].x; Kt[(dc+1)*KT_S+lr4]=kreg[u].y;
            Kt[(dc+2)*KT_S+lr4]=kreg[u].z; Kt[(dc+3)*KT_S+lr4]=kreg[u].w;
            *reinterpret_cast<float4*>(&Vs[lr4*VS_S + dc]) = vreg[u];
        }
        __syncthreads();

        unsigned long long s2[4][4];
        #pragma unroll
        for (int i=0;i<4;i++)
            #pragma unroll
            for (int c=0;c<4;c++) s2[i][c]=0ull;
        #pragma unroll 8
        for (int d=0; d<HD; d++){
            const float* qr_ = &Qt[d*QT_S + (ty<<3)];
            ulonglong2 qa = *reinterpret_cast<const ulonglong2*>(qr_);
            ulonglong2 qb = *reinterpret_cast<const ulonglong2*>(qr_+4);
            float4 kv = *reinterpret_cast<const float4*>(&Kt[d*KT_S + (tx<<2)]);
            unsigned long long k0=pk2(kv.x,kv.x), k1=pk2(kv.y,kv.y);
            unsigned long long k2=pk2(kv.z,kv.z), k3=pk2(kv.w,kv.w);
            fma2(s2[0][0],qa.x,k0); fma2(s2[0][1],qa.x,k1);
            fma2(s2[0][2],qa.x,k2); fma2(s2[0][3],qa.x,k3);
            fma2(s2[1][0],qa.y,k0); fma2(s2[1][1],qa.y,k1);
            fma2(s2[1][2],qa.y,k2); fma2(s2[1][3],qa.y,k3);
            fma2(s2[2][0],qb.x,k0); fma2(s2[2][1],qb.x,k1);
            fma2(s2[2][2],qb.x,k2); fma2(s2[2][3],qb.x,k3);
            fma2(s2[3][0],qb.y,k0); fma2(s2[3][1],qb.y,k1);
            fma2(s2[3][2],qb.y,k2); fma2(s2[3][3],qb.y,k3);
        }

        float p[8][4];
        #pragma unroll
        for (int rp=0;rp<4;rp++)
            #pragma unroll
            for (int c=0;c<4;c++){
                float2 t = upk(s2[rp][c]);
                p[2*rp  ][c] = t.x*0.125f;
                p[2*rp+1][c] = t.y*0.125f;
            }
        float cf[8];
        #pragma unroll
        for (int qr=0;qr<8;qr++){
            float mx = fmaxf(fmaxf(p[qr][0],p[qr][1]), fmaxf(p[qr][2],p[qr][3]));
            #pragma unroll
            for (int m=8;m>0;m>>=1) mx = fmaxf(mx, __shfl_xor_sync(0xffffffffu, mx, m));
            float mn = fmaxf(m_i[qr], mx);
            cf[qr] = __expf(m_i[qr] - mn);
            m_i[qr] = mn;
            float s = 0.f;
            #pragma unroll
            for (int c=0;c<4;c++){ p[qr][c] = __expf(p[qr][c]-mn); s += p[qr][c]; }
            #pragma unroll
            for (int m=8;m>0;m>>=1) s += __shfl_xor_sync(0xffffffffu, s, m);
            l_i[qr] = l_i[qr]*cf[qr] + s;
        }
        #pragma unroll
        for (int rp=0;rp<4;rp++){
            unsigned long long c2 = pk2(cf[2*rp], cf[2*rp+1]);
            mul2(o2[rp][0],c2); mul2(o2[rp][1],c2);
            mul2(o2[rp][2],c2); mul2(o2[rp][3],c2);
        }
        __syncthreads();
        #pragma unroll
        for (int c=0;c<4;c++)
            #pragma unroll
            for (int rp=0;rp<4;rp++)
                *reinterpret_cast<unsigned long long*>(
                    &Pt[((tx<<2)+c)*PT_S + (ty<<3) + rp*2]) = pk2(p[2*rp][c], p[2*rp+1][c]);
        __syncthreads();

        #pragma unroll 8
        for (int kj=0; kj<64; kj++){
            const float* pr = &Pt[kj*PT_S + (ty<<3)];
            ulonglong2 pa = *reinterpret_cast<const ulonglong2*>(pr);
            ulonglong2 pb = *reinterpret_cast<const ulonglong2*>(pr+4);
            float4 vv = *reinterpret_cast<const float4*>(&Vs[kj*VS_S + (tx<<2)]);
            unsigned long long v0=pk2(vv.x,vv.x), v1=pk2(vv.y,vv.y);
            unsigned long long v2=pk2(vv.z,vv.z), v3=pk2(vv.w,vv.w);
            fma2(o2[0][0],pa.x,v0); fma2(o2[0][1],pa.x,v1);
            fma2(o2[0][2],pa.x,v2); fma2(o2[0][3],pa.x,v3);
            fma2(o2[1][0],pa.y,v0); fma2(o2[1][1],pa.y,v1);
            fma2(o2[1][2],pa.y,v2); fma2(o2[1][3],pa.y,v3);
            fma2(o2[2][0],pb.x,v0); fma2(o2[2][1],pb.x,v1);
            fma2(o2[2][2],pb.x,v2); fma2(o2[2][3],pb.x,v3);
            fma2(o2[3][0],pb.y,v0); fma2(o2[3][1],pb.y,v1);
            fma2(o2[3][2],pb.y,v2); fma2(o2[3][3],pb.y,v3);
        }
    }

    #pragma unroll
    for (int rp=0;rp<4;rp++){
        #pragma unroll
        for (int p=0;p<2;p++){
            int qr = rp*2 + p;
            float inv = 1.0f / l_i[qr];
            int row = b*SEQ + q0 + (ty<<3) + qr;
            float2 t0 = upk(o2[rp][0]); float2 t1 = upk(o2[rp][1]);
            float2 t2 = upk(o2[rp][2]); float2 t3 = upk(o2[rp][3]);
            float4 ov;
            ov.x = (p ? t0.y : t0.x) * inv;
            ov.y = (p ? t1.y : t1.x) * inv;
            ov.z = (p ? t2.y : t2.x) * inv;
            ov.w = (p ? t3.y : t3.x) * inv;
            *reinterpret_cast<float4*>(&out[row*DIM + h*HD + (tx<<2)]) = ov;
        }
    }
}

// ---------------- launch -----------------------------------------------------
extern "C" void kernel_launch(void* const* d_in, const int* in_sizes, int n_in,
                              void* d_out, int out_size)
{
    const float* x     =(const float*)d_in[0];
    const float* ln1g  =(const float*)d_in[1];
    const float* ln1b  =(const float*)d_in[2];
    const float* qkvw  =(const float*)d_in[3];
    const float* qkvbi =(const float*)d_in[4];
    const float* projw =(const float*)d_in[5];
    const float* projb =(const float*)d_in[6];
    const float* cqkvw =(const float*)d_in[7];
    const float* cqkvb =(const float*)d_in[8];
    const float* cprojw=(const float*)d_in[9];
    const float* cprojb=(const float*)d_in[10];
    const float* cf1w  =(const float*)d_in[11];
    const float* cf1b  =(const float*)d_in[12];
    const float* cf2w  =(const float*)d_in[13];
    const float* cf2b  =(const float*)d_in[14];
    const float* P     =(const float*)d_in[15];
    const float* ln2g  =(const float*)d_in[16];
    const float* ln2b  =(const float*)d_in[17];
    const float* f1w   =(const float*)d_in[18];
    const float* f1b   =(const float*)d_in[19];
    const float* f2w   =(const float*)d_in[20];
    const float* f2b   =(const float*)d_in[21];

    float *n1,*un,*qkvb,*ao,*y,*cph,*zin,*xa,*n2,*hid,*Pn;
    __nv_bfloat16 *Ahi,*Alo,*Whi,*Wlo;
    cudaGetSymbolAddress((void**)&n1,  g_n1);
    cudaGetSymbolAddress((void**)&un,  g_un);
    cudaGetSymbolAddress((void**)&qkvb,g_qkv);
    cudaGetSymbolAddress((void**)&ao,  g_ao);
    cudaGetSymbolAddress((void**)&y,   g_y);
    cudaGetSymbolAddress((void**)&cph, g_cph);
    cudaGetSymbolAddress((void**)&zin, g_zin);
    cudaGetSymbolAddress((void**)&xa,  g_xa);
    cudaGetSymbolAddress((void**)&n2,  g_n2);
    cudaGetSymbolAddress((void**)&hid, g_hid);
    cudaGetSymbolAddress((void**)&Pn,  g_Pn);
    cudaGetSymbolAddress((void**)&Ahi, g_Ahi);
    cudaGetSymbolAddress((void**)&Alo, g_Alo);
    cudaGetSymbolAddress((void**)&Whi, g_Whi);
    cudaGetSymbolAddress((void**)&Wlo, g_Wlo);

    float* outx = (float*)d_out;
    float* dmap = outx + X_ELEMS;

    cudaFuncSetAttribute(attn_kernel,
        cudaFuncAttributeMaxDynamicSharedMemorySize, ATTN_SMEM2);

    pn_kernel<<<KP,256>>>(P, Pn);
    ln_kernel<<<NTOK,256>>>(x, ln1g, ln1b, n1, un);

    // qkv = n1 @ qkv_w^T + b   (tensor)
    cvt_split<<<2048,256>>>(n1,   Ahi, Alo, (NTOK*DIM)/4);
    cvt_split<<<512, 256>>>(qkvw, Whi, Wlo, (3*DIM*DIM)/4);
    gemm_mma<EPI_NONE><<<dim3(18,64),256>>>(Ahi,Alo,Whi,Wlo, qkvbi, qkvb, NTOK, 3*DIM, DIM, 0, 0);
    attn_kernel<<<dim3(SEQ/128, BATCH*NH),256,ATTN_SMEM2>>>(qkvb, ao);
    // y = ao @ proj_w^T + b
    cvt_split<<<2048,256>>>(ao,    Ahi, Alo, (NTOK*DIM)/4);
    cvt_split<<<512, 256>>>(projw, Whi, Wlo, (DIM*DIM)/4);
    gemm_mma<EPI_NONE><<<dim3(6,64),256>>>(Ahi,Alo,Whi,Wlo, projb, y, NTOK, DIM, DIM, 0, 0);
    // dmap = un @ Pn^T  (N=64, SIMT)
    gemm_tn<EPI_NONE><<<dim3(1,128),256>>>(un, Pn, (const float*)0, dmap, NTOK, KP, DIM, 0, 0);
    // cph = gelu(dmap @ cf1^T + b)  (N=64, SIMT)
    gemm_tn<EPI_GELU><<<dim3(1,128),256>>>(dmap, cf1w, cf1b, cph, NTOK, KP, KP, 0, 0);
    // zin = cph @ cf2^T + b  (K=64, tensor)
    cvt_split<<<512, 256>>>(cph,  Ahi, Alo, (NTOK*KP)/4);
    cvt_split<<<256, 256>>>(cf2w, Whi, Wlo, (DIM*KP)/4);
    gemm_mma<EPI_NONE><<<dim3(6,64),256>>>(Ahi,Alo,Whi,Wlo, cf2b, zin, NTOK, DIM, KP, 0, 0);
    // qkv2 = zin @ c_qkv^T + b
    cvt_split<<<2048,256>>>(zin,   Ahi, Alo, (NTOK*DIM)/4);
    cvt_split<<<512, 256>>>(cqkvw, Whi, Wlo, (3*DIM*DIM)/4);
    gemm_mma<EPI_NONE><<<dim3(18,64),256>>>(Ahi,Alo,Whi,Wlo, cqkvb, qkvb, NTOK, 3*DIM, DIM, 0, 0);
    attn_kernel<<<dim3(SEQ/128, BATCH*NH),256,ATTN_SMEM2>>>(qkvb, ao);
    // xa = ao @ c_proj^T + b + x + y
    cvt_split<<<2048,256>>>(ao,     Ahi, Alo, (NTOK*DIM)/4);
    cvt_split<<<512, 256>>>(cprojw, Whi, Wlo, (DIM*DIM)/4);
    gemm_mma<EPI_RES><<<dim3(6,64),256>>>(Ahi,Alo,Whi,Wlo, cprojb, xa, NTOK, DIM, DIM, x, y);
    ln_kernel<<<NTOK,256>>>(xa, ln2g, ln2b, n2, (float*)0);
    // hid = gelu(n2 @ fc1^T + b)
    cvt_split<<<2048,256>>>(n2,  Ahi, Alo, (NTOK*DIM)/4);
    cvt_split<<<1024,256>>>(f1w, Whi, Wlo, (MLPH*DIM)/4);
    gemm_mma<EPI_GELU><<<dim3(24,64),256>>>(Ahi,Alo,Whi,Wlo, f1b, hid, NTOK, MLPH, DIM, 0, 0);
    // out_x = hid @ fc2^T + b + xa
    cvt_split<<<4096,256>>>(hid, Ahi, Alo, (NTOK*MLPH)/4);
    cvt_split<<<1024,256>>>(f2w, Whi, Wlo, (DIM*MLPH)/4);
    gemm_mma<EPI_RES><<<dim3(6,64),256>>>(Ahi,Alo,Whi,Wlo, f2b, outx, NTOK, DIM, MLPH, xa, 0);
}